// round 1
// baseline (speedup 1.0000x reference)
#include <cuda_runtime.h>
#include <cstdint>

// ---------------------------------------------------------------------------
// SimpleESN: h_t = (1-a) h_{t-1} + a * tanh(W_in x_t + W h_{t-1})
// x: [2048,128] f32, W_in: [4096,128] f32, W: [4096,4096] f32 (~10% dense)
// out: [2048,4096] f32 (the states; out[t] IS h_t, so it doubles as h storage)
//
// Strategy: persistent kernel, 128 co-resident blocks, software grid barrier.
// W compacted once per replay into per-row ELL (val f32 + col u32, 8B/nz),
// block<->row affinity fixed so each SM's ELL slice (~110KB) stays L1-hot.
// ---------------------------------------------------------------------------

#define T_STEPS 2048
#define N_RES   4096
#define N_IN    128
#define LEAK    0.3f

#define BLOCKS  128
#define THREADS 512
#define WARPS   (THREADS / 32)                 // 16
#define ROWS_PER_BLOCK (N_RES / BLOCKS)        // 32
#define ROW_CAP 576                            // mean nnz/row=409.6, sd=19.2; 576 ~ 8.7 sigma

// Scratch: static device globals (allowed; no runtime allocation).
__device__ uint2        g_ell[(size_t)N_RES * ROW_CAP];   // ~18.9 MB
__device__ unsigned int g_barrier;

__global__ void esn_reset_kernel() {
    g_barrier = 0u;
}

__global__ void __launch_bounds__(THREADS, 1)
esn_kernel(const float* __restrict__ x,
           const float* __restrict__ W_in,
           const float* __restrict__ W,
           float* __restrict__ out)
{
    __shared__ float h_sm[N_RES];          // 16 KB: full h_{t-1}
    __shared__ float x_sm[N_IN];           // 512 B: x_t
    __shared__ int   rowlen_sm[ROWS_PER_BLOCK];

    const int tid  = threadIdx.x;
    const int wid  = tid >> 5;
    const int lane = tid & 31;
    const int row0 = blockIdx.x * ROWS_PER_BLOCK;

    // ------------------------------------------------------------------
    // Phase 1: build ELL for this block's rows (one warp per row, 2 rows/warp)
    // Columns come out ascending -> coalesced LDG + spread smem banks later.
    // ------------------------------------------------------------------
    for (int rr = wid; rr < ROWS_PER_BLOCK; rr += WARPS) {
        const int row = row0 + rr;
        const float* wrow = W + (size_t)row * N_RES;
        uint2* ell = g_ell + (size_t)row * ROW_CAP;
        int cnt = 0;
        #pragma unroll 4
        for (int c0 = 0; c0 < N_RES; c0 += 32) {
            float v = wrow[c0 + lane];
            unsigned m = __ballot_sync(0xffffffffu, v != 0.0f);
            if (v != 0.0f) {
                int pos = cnt + __popc(m & ((1u << lane) - 1u));
                if (pos < ROW_CAP)
                    ell[pos] = make_uint2(__float_as_uint(v), (unsigned)(c0 + lane));
            }
            cnt += __popc(m);
        }
        if (lane == 0) rowlen_sm[rr] = (cnt < ROW_CAP) ? cnt : ROW_CAP;
    }
    __syncthreads();

    // ------------------------------------------------------------------
    // Phase 2: time recurrence with grid-wide barrier between steps
    // ------------------------------------------------------------------
    const float a  = LEAK;
    const float ia = 1.0f - LEAK;
    unsigned int target = 0;

    for (int t = 0; t < T_STEPS; ++t) {
        // x_t -> smem
        if (tid < N_IN) x_sm[tid] = __ldg(x + (size_t)t * N_IN + tid);

        // h_{t-1} -> smem (bypass L1: written by other SMs last step)
        if (t == 0) {
            for (int i = tid; i < N_RES; i += THREADS) h_sm[i] = 0.0f;
        } else {
            const float* hprev = out + (size_t)(t - 1) * N_RES;
            #pragma unroll
            for (int i = tid * 4; i < N_RES; i += THREADS * 4) {
                float4 v = __ldcg((const float4*)(hprev + i));
                *(float4*)(h_sm + i) = v;
            }
        }
        __syncthreads();

        // each warp: 2 rows
        for (int rr = wid; rr < ROWS_PER_BLOCK; rr += WARPS) {
            const int row = row0 + rr;

            // dense input part: W_in[row] . x_t (128 MACs over 32 lanes, float4)
            float4 w4 = __ldg((const float4*)(W_in + (size_t)row * N_IN) + lane);
            float4 x4 = *(const float4*)(x_sm + lane * 4);
            float sum = w4.x * x4.x + w4.y * x4.y + w4.z * x4.z + w4.w * x4.w;

            // sparse recurrent part: gather h from smem
            const int len = rowlen_sm[rr];
            const uint2* ell = g_ell + (size_t)row * ROW_CAP;
            int j = lane;
            #pragma unroll 4
            for (; j < len; j += 32) {
                uint2 e = ell[j];
                sum = fmaf(__uint_as_float(e.x), h_sm[e.y], sum);
            }

            // warp reduce
            #pragma unroll
            for (int o = 16; o > 0; o >>= 1)
                sum += __shfl_down_sync(0xffffffffu, sum, o);

            if (lane == 0) {
                float hn = ia * h_sm[row] + a * tanhf(sum);
                out[(size_t)t * N_RES + row] = hn;
            }
        }

        // grid barrier (release h_t writes; skip after the final step)
        if (t < T_STEPS - 1) {
            __syncthreads();
            __threadfence();
            if (tid == 0) {
                atomicAdd(&g_barrier, 1u);
                target += BLOCKS;
                while (*((volatile unsigned int*)&g_barrier) < target) { }
            }
            __syncthreads();
            __threadfence();
        } else {
            __syncthreads();
        }
    }
}

extern "C" void kernel_launch(void* const* d_in, const int* in_sizes, int n_in,
                              void* d_out, int out_size)
{
    const float* x    = (const float*)d_in[0];   // [2048, 128]
    const float* W_in = (const float*)d_in[1];   // [4096, 128]
    const float* W    = (const float*)d_in[2];   // [4096, 4096]
    float* out        = (float*)d_out;           // [2048, 4096]

    esn_reset_kernel<<<1, 1>>>();
    esn_kernel<<<BLOCKS, THREADS>>>(x, W_in, W, out);
}

// round 2
// speedup vs baseline: 1.5183x; 1.5183x over previous
#include <cuda_runtime.h>
#include <cstdint>

// ---------------------------------------------------------------------------
// SimpleESN: h_t = (1-a) h_{t-1} + a * tanh(W_in x_t + W h_{t-1})
// x: [2048,128] f32, W_in: [4096,128] f32, W: [4096,4096] f32 (~10% dense)
// out: [2048,4096] f32  (out[t] IS h_t -> doubles as h storage)
//
// Persistent 128-block kernel, software grid barrier with release/acquire
// atomics (NO __threadfence -> no CCTL.IVALL -> per-SM ELL slice stays
// L1-resident across all 2048 steps). h traffic goes through L2 via st.cg /
// ld.cg so no L1 invalidation is ever required.
// ---------------------------------------------------------------------------

#define T_STEPS 2048
#define N_RES   4096
#define N_IN    128
#define LEAK    0.3f

#define BLOCKS  128
#define THREADS 1024
#define WARPS   (THREADS / 32)                 // 32
#define ROWS_PER_BLOCK (N_RES / BLOCKS)        // 32 -> exactly 1 row per warp
#define ROW_CAP 576                            // mean nnz/row ~409.6, sd ~19.2

__device__ uint2        g_ell[(size_t)N_RES * ROW_CAP];   // ~18.9 MB scratch
__device__ unsigned int g_barrier;

__global__ void esn_reset_kernel() {
    g_barrier = 0u;
}

__device__ __forceinline__ unsigned int ld_acquire_gpu(const unsigned int* p) {
    unsigned int v;
    asm volatile("ld.acquire.gpu.global.u32 %0, [%1];" : "=r"(v) : "l"(p));
    return v;
}

__device__ __forceinline__ void red_release_gpu_add(unsigned int* p, unsigned int v) {
    asm volatile("red.release.gpu.global.add.u32 [%0], %1;" :: "l"(p), "r"(v) : "memory");
}

__global__ void __launch_bounds__(THREADS, 1)
esn_kernel(const float* __restrict__ x,
           const float* __restrict__ W_in,
           const float* __restrict__ W,
           float* __restrict__ out)
{
    __shared__ float h_sm[N_RES];              // 16 KB: full h_{t-1}

    const int tid  = threadIdx.x;
    const int wid  = tid >> 5;
    const int lane = tid & 31;
    const int row0 = blockIdx.x * ROWS_PER_BLOCK;
    const int row  = row0 + wid;               // this warp's row (1 row/warp)

    // ------------------------------------------------------------------
    // Phase 1: compact this block's 32 rows of W into ELL (one row/warp).
    // Ascending columns -> coalesced writes; slice is read by this SM only.
    // ------------------------------------------------------------------
    int my_len = 0;
    {
        const float* wrow = W + (size_t)row * N_RES;
        uint2* ell = g_ell + (size_t)row * ROW_CAP;
        int cnt = 0;
        #pragma unroll 4
        for (int c0 = 0; c0 < N_RES; c0 += 32) {
            float v = wrow[c0 + lane];
            unsigned m = __ballot_sync(0xffffffffu, v != 0.0f);
            if (v != 0.0f) {
                int pos = cnt + __popc(m & ((1u << lane) - 1u));
                if (pos < ROW_CAP)
                    ell[pos] = make_uint2(__float_as_uint(v), (unsigned)(c0 + lane));
            }
            cnt += __popc(m);
        }
        my_len = (cnt < ROW_CAP) ? cnt : ROW_CAP;
    }
    __syncthreads();

    // ------------------------------------------------------------------
    // Phase 2: time recurrence
    // ------------------------------------------------------------------
    const float a  = LEAK;
    const float ia = 1.0f - LEAK;
    const float4* win4 = (const float4*)(W_in + (size_t)row * N_IN);
    const uint2*  ell  = g_ell + (size_t)row * ROW_CAP;

    for (int t = 0; t < T_STEPS; ++t) {
        // ---- h-independent dense part first (off the critical path) ----
        float4 w4 = __ldg(win4 + lane);
        float4 x4 = __ldg((const float4*)(x + (size_t)t * N_IN) + lane);
        float sum = w4.x * x4.x + w4.y * x4.y + w4.z * x4.z + w4.w * x4.w;

        // ---- wait until h_{t-1} is published by all blocks ----
        if (t > 0) {
            if (tid == 0) {
                const unsigned int want = (unsigned int)t * BLOCKS;
                while (ld_acquire_gpu(&g_barrier) < want) { }
            }
            __syncthreads();   // S1: spin done; also all warps done with old h_sm
        }

        // ---- stage h_{t-1} into smem (L2 path; never needs L1 coherence) ----
        if (t == 0) {
            for (int i = tid; i < N_RES; i += THREADS) h_sm[i] = 0.0f;
        } else {
            const float4* hprev = (const float4*)(out + (size_t)(t - 1) * N_RES);
            float4 v = __ldcg(hprev + tid);    // 1024 threads x 16B = 16 KB
            *(float4*)(h_sm + tid * 4) = v;
        }
        __syncthreads();       // S2: h_sm ready

        // ---- sparse recurrent gather (ELL in L1, h in smem) ----
        #pragma unroll 4
        for (int j = lane; j < my_len; j += 32) {
            uint2 e = ell[j];
            sum = fmaf(__uint_as_float(e.x), h_sm[e.y], sum);
        }

        // ---- warp reduce, leak, publish ----
        #pragma unroll
        for (int o = 16; o > 0; o >>= 1)
            sum += __shfl_down_sync(0xffffffffu, sum, o);

        if (lane == 0) {
            float hn = ia * h_sm[row] + a * tanhf(sum);
            __stcg(out + (size_t)t * N_RES + row, hn);
        }

        if (t < T_STEPS - 1) {
            __syncthreads();   // S3: all 32 rows of this block written
            if (tid == 0) red_release_gpu_add(&g_barrier, 1u);
        }
    }
}

extern "C" void kernel_launch(void* const* d_in, const int* in_sizes, int n_in,
                              void* d_out, int out_size)
{
    const float* x    = (const float*)d_in[0];   // [2048, 128]
    const float* W_in = (const float*)d_in[1];   // [4096, 128]
    const float* W    = (const float*)d_in[2];   // [4096, 4096]
    float* out        = (float*)d_out;           // [2048, 4096]

    esn_reset_kernel<<<1, 1>>>();
    esn_kernel<<<BLOCKS, THREADS>>>(x, W_in, W, out);
}

// round 3
// speedup vs baseline: 1.7484x; 1.1516x over previous
#include <cuda_runtime.h>
#include <cstdint>

// ---------------------------------------------------------------------------
// SimpleESN: h_t = (1-a) h_{t-1} + a * tanh(W_in x_t + W h_{t-1})
// x: [2048,128] f32, W_in: [4096,128] f32, W: [4096,4096] f32 (~10% dense)
// out: [2048,4096] f32  (out[t] IS h_t -> doubles as h storage)
//
// Persistent 128-block kernel. Critical design rule for this round:
// ZERO L1-invalidating operations in the step loop (no __threadfence, no
// ld.acquire -> no CCTL.IVALL). All inter-block data (h, barrier counter)
// moves via L2-only ops (st.cg / ld.cg / red.release / ld.relaxed.gpu).
// All L1-cached data (per-SM ELL slice, x, W_in) is immutable during the
// loop, so no acquire is needed and the ELL slice stays L1-resident for
// all 2048 steps.
// ---------------------------------------------------------------------------

#define T_STEPS 2048
#define N_RES   4096
#define N_IN    128
#define LEAK    0.3f

#define BLOCKS  128
#define THREADS 1024
#define WARPS   (THREADS / 32)                 // 32
#define ROWS_PER_BLOCK (N_RES / BLOCKS)        // 32 -> exactly 1 row per warp
#define ROW_CAP 576                            // mean nnz/row ~409.6, sd ~19.2

__device__ uint2        g_ell[(size_t)N_RES * ROW_CAP];   // ~18.9 MB scratch
__device__ unsigned int g_barrier;

__global__ void esn_reset_kernel() {
    g_barrier = 0u;
}

// Strong gpu-scope relaxed load: routed to L2 (coherent), NO L1 invalidate.
__device__ __forceinline__ unsigned int ld_relaxed_gpu(const unsigned int* p) {
    unsigned int v;
    asm volatile("ld.relaxed.gpu.global.u32 %0, [%1];" : "=r"(v) : "l"(p) : "memory");
    return v;
}

// Release-RED: orders this thread's prior (L2-routed) stores before the
// counter bump. Fire-and-forget; no L1 invalidate.
__device__ __forceinline__ void red_release_gpu_add(unsigned int* p, unsigned int v) {
    asm volatile("red.release.gpu.global.add.u32 [%0], %1;" :: "l"(p), "r"(v) : "memory");
}

__global__ void __launch_bounds__(THREADS, 1)
esn_kernel(const float* __restrict__ x,
           const float* __restrict__ W_in,
           const float* __restrict__ W,
           float* __restrict__ out)
{
    __shared__ float h_sm[N_RES];              // 16 KB: full h_{t-1}

    const int tid  = threadIdx.x;
    const int wid  = tid >> 5;
    const int lane = tid & 31;
    const int row0 = blockIdx.x * ROWS_PER_BLOCK;
    const int row  = row0 + wid;               // this warp's row (1 row/warp)

    // ------------------------------------------------------------------
    // Phase 1: compact this block's 32 rows of W into ELL (one row/warp).
    // The slice is written and read ONLY by this SM, and never modified
    // after this phase -> L1 copies can never go stale.
    // ------------------------------------------------------------------
    int my_len = 0;
    {
        const float* wrow = W + (size_t)row * N_RES;
        uint2* ell = g_ell + (size_t)row * ROW_CAP;
        int cnt = 0;
        #pragma unroll 4
        for (int c0 = 0; c0 < N_RES; c0 += 32) {
            float v = wrow[c0 + lane];
            unsigned m = __ballot_sync(0xffffffffu, v != 0.0f);
            if (v != 0.0f) {
                int pos = cnt + __popc(m & ((1u << lane) - 1u));
                if (pos < ROW_CAP)
                    ell[pos] = make_uint2(__float_as_uint(v), (unsigned)(c0 + lane));
            }
            cnt += __popc(m);
        }
        my_len = (cnt < ROW_CAP) ? cnt : ROW_CAP;
    }
    __syncthreads();

    // ------------------------------------------------------------------
    // Phase 2: time recurrence
    // ------------------------------------------------------------------
    const float a  = LEAK;
    const float ia = 1.0f - LEAK;
    const float4* win4 = (const float4*)(W_in + (size_t)row * N_IN);
    const uint2*  ell  = g_ell + (size_t)row * ROW_CAP;

    for (int t = 0; t < T_STEPS; ++t) {
        // ---- h-independent dense part first (off the critical path) ----
        float4 w4 = __ldg(win4 + lane);
        float4 x4 = __ldg((const float4*)(x + (size_t)t * N_IN) + lane);
        float sum = w4.x * x4.x + w4.y * x4.y + w4.z * x4.z + w4.w * x4.w;

        // ---- wait until h_{t-1} is published by all blocks ----
        if (t > 0) {
            if (tid == 0) {
                const unsigned int want = (unsigned int)t * BLOCKS;
                while (ld_relaxed_gpu(&g_barrier) < want) { }
            }
            __syncthreads();   // S1: spin done; all warps done with old h_sm
        }

        // ---- stage h_{t-1} into smem (ld.cg: L2-direct, always coherent) ----
        if (t == 0) {
            for (int i = tid; i < N_RES; i += THREADS) h_sm[i] = 0.0f;
        } else {
            const float4* hprev = (const float4*)(out + (size_t)(t - 1) * N_RES);
            float4 v = __ldcg(hprev + tid);    // 1024 threads x 16B = 16 KB
            *(float4*)(h_sm + tid * 4) = v;
        }
        __syncthreads();       // S2: h_sm ready

        // ---- sparse recurrent gather (ELL in L1, h in smem) ----
        #pragma unroll 4
        for (int j = lane; j < my_len; j += 32) {
            uint2 e = ell[j];
            sum = fmaf(__uint_as_float(e.x), h_sm[e.y], sum);
        }

        // ---- warp reduce, leak, publish ----
        #pragma unroll
        for (int o = 16; o > 0; o >>= 1)
            sum += __shfl_down_sync(0xffffffffu, sum, o);

        if (lane == 0) {
            float hn = ia * h_sm[row] + a * tanhf(sum);
            __stcg(out + (size_t)t * N_RES + row, hn);
        }

        if (t < T_STEPS - 1) {
            __syncthreads();   // S3: all 32 rows of this block written (st.cg in L2)
            if (tid == 0) red_release_gpu_add(&g_barrier, 1u);
        }
    }
}

extern "C" void kernel_launch(void* const* d_in, const int* in_sizes, int n_in,
                              void* d_out, int out_size)
{
    const float* x    = (const float*)d_in[0];   // [2048, 128]
    const float* W_in = (const float*)d_in[1];   // [4096, 128]
    const float* W    = (const float*)d_in[2];   // [4096, 4096]
    float* out        = (float*)d_out;           // [2048, 4096]

    esn_reset_kernel<<<1, 1>>>();
    esn_kernel<<<BLOCKS, THREADS>>>(x, W_in, W, out);
}

// round 5
// speedup vs baseline: 2.0110x; 1.1502x over previous
#include <cuda_runtime.h>
#include <cstdint>

// ---------------------------------------------------------------------------
// SimpleESN: h_t = (1-a) h_{t-1} + a * tanh(W_in x_t + W h_{t-1})
//
// R5 = R4 with the sm_103-unsupported redux.sync.add.f32 replaced by a
// butterfly SHFL reduction. Core ideas unchanged:
//  - persistent 128 blocks, L2-only barrier (no L1 invalidation ever)
//  - per-SM ELL slice stays L1-resident all 2048 steps
//  - bank round-robin reorder at build time -> conflict-free smem gather
//  - SoA float2 vals + packed u16x2 cols (halves gather LDG wavefronts)
// ---------------------------------------------------------------------------

#define T_STEPS 2048
#define N_RES   4096
#define N_IN    128
#define LEAK    0.3f

#define BLOCKS  128
#define THREADS 1024
#define WARPS   (THREADS / 32)                 // 32
#define ROWS_PER_BLOCK (N_RES / BLOCKS)        // 32 -> 1 row per warp
#define ROW_CAP 576                            // multiple of 64; nnz/row ~410 +- 19

__device__ uint2          g_tmp[(size_t)N_RES * ROW_CAP];   // build scratch
__device__ float          g_val[(size_t)N_RES * ROW_CAP];
__device__ unsigned short g_col[(size_t)N_RES * ROW_CAP];
__device__ unsigned int   g_barrier;

__global__ void esn_reset_kernel() { g_barrier = 0u; }

__device__ __forceinline__ unsigned int ld_relaxed_gpu(const unsigned int* p) {
    unsigned int v;
    asm volatile("ld.relaxed.gpu.global.u32 %0, [%1];" : "=r"(v) : "l"(p) : "memory");
    return v;
}
__device__ __forceinline__ void red_release_gpu_add(unsigned int* p, unsigned int v) {
    asm volatile("red.release.gpu.global.add.u32 [%0], %1;" :: "l"(p), "r"(v) : "memory");
}

__global__ void __launch_bounds__(THREADS, 1)
esn_kernel(const float* __restrict__ x,
           const float* __restrict__ W_in,
           const float* __restrict__ W,
           float* __restrict__ out)
{
    __shared__ float h_sm[N_RES];                      // 16 KB
    __shared__ int   cnt_sm[WARPS * 32];               // 4 KB: per-warp bank bins

    const int tid  = threadIdx.x;
    const int wid  = tid >> 5;
    const int lane = tid & 31;
    const int row0 = blockIdx.x * ROWS_PER_BLOCK;
    const int row  = row0 + wid;
    const size_t rowbase = (size_t)row * ROW_CAP;

    // ------------------------------------------------------------------
    // Phase 1: compact row -> g_tmp (ascending cols), count nnz
    // ------------------------------------------------------------------
    int len = 0;
    {
        const float* wrow = W + (size_t)row * N_RES;
        uint2* tmp = g_tmp + rowbase;
        int cnt = 0;
        #pragma unroll 4
        for (int c0 = 0; c0 < N_RES; c0 += 32) {
            float v = wrow[c0 + lane];
            unsigned m = __ballot_sync(0xffffffffu, v != 0.0f);
            if (v != 0.0f) {
                int pos = cnt + __popc(m & ((1u << lane) - 1u));
                if (pos < ROW_CAP)
                    tmp[pos] = make_uint2(__float_as_uint(v), (unsigned)(c0 + lane));
            }
            cnt += __popc(m);
        }
        len = (cnt < ROW_CAP) ? cnt : ROW_CAP;
    }
    const int lenp = (len + 63) & ~63;                 // padded to 64

    // ------------------------------------------------------------------
    // Phase 1.5: bank round-robin reorder, SoA scatter
    //   key(e) = (m, bank): m = index within its bank bin.
    //   rank(pos) sorted by key -> iteration k's lanes see distinct banks.
    //   storage sigma: pos = 64k + 32c + l  ->  s = 64k + 2l + c, so a lane's
    //   float2/u16x2 pair = bank-slot l of m-groups 2k and 2k+1.
    // ------------------------------------------------------------------
    {
        int* cnt = cnt_sm + wid * 32;
        cnt[lane] = 0;
        __syncwarp();

        uint2* tmp = g_tmp + rowbase;
        // pass A: per-entry within-bank index m (packed into high bits of .y)
        for (int j = lane; j < len; j += 32) {
            uint2 e = tmp[j];
            int b = (int)(e.y & 31u);
            int m = atomicAdd(&cnt[b], 1);
            tmp[j].y = e.y | ((unsigned)m << 16);
        }
        __syncwarp();

        // zero-pad the SoA storage up to lenp
        for (int j = lane; j < lenp; j += 32) {
            g_val[rowbase + j] = 0.0f;
            g_col[rowbase + j] = 0;
        }
        __syncwarp();

        // pass B: rank + sigma + scatter
        for (int j = lane; j < len; j += 32) {
            uint2 e = tmp[j];
            int col = (int)(e.y & 0xFFFu);
            int m   = (int)(e.y >> 16);
            int b   = col & 31;
            int pos = 0;
            #pragma unroll
            for (int b2 = 0; b2 < 32; ++b2) {
                int c = cnt[b2];
                pos += (c < m ? c : m) + (int)((b2 < b) && (c > m));
            }
            int s = (pos & ~63) | ((pos & 31) << 1) | ((pos >> 5) & 1);
            g_val[rowbase + s] = __uint_as_float(e.x);
            g_col[rowbase + s] = (unsigned short)col;
        }
    }
    __syncthreads();

    // ------------------------------------------------------------------
    // Phase 2: time recurrence
    // ------------------------------------------------------------------
    const float a  = LEAK;
    const float ia = 1.0f - LEAK;
    const float4* win4 = (const float4*)(W_in + (size_t)row * N_IN);
    const float2*       vp = (const float2*)(g_val + rowbase);
    const unsigned int* cp = (const unsigned int*)(g_col + rowbase);
    const int iters = lenp >> 6;                       // 64 entries per iter

    for (int t = 0; t < T_STEPS; ++t) {
        // h-independent dense part (off the critical path)
        float4 w4 = __ldg(win4 + lane);
        float4 x4 = __ldg((const float4*)(x + (size_t)t * N_IN) + lane);
        float sum0 = w4.x * x4.x + w4.y * x4.y;
        float sum1 = w4.z * x4.z + w4.w * x4.w;

        // wait for h_{t-1}
        if (t > 0) {
            if (tid == 0) {
                const unsigned int want = (unsigned int)t * BLOCKS;
                while (ld_relaxed_gpu(&g_barrier) < want) { }
            }
            __syncthreads();   // spin done; old h_sm no longer in use
        }

        // stage h_{t-1} into smem (L2-direct, always coherent)
        if (t == 0) {
            for (int i = tid; i < N_RES; i += THREADS) h_sm[i] = 0.0f;
        } else {
            const float4* hprev = (const float4*)(out + (size_t)(t - 1) * N_RES);
            float4 v = __ldcg(hprev + tid);
            *(float4*)(h_sm + tid * 4) = v;
        }
        __syncthreads();

        // bank-conflict-free sparse gather
        #pragma unroll 2
        for (int k = 0; k < iters; ++k) {
            float2       v  = vp[(k << 5) + lane];
            unsigned int cc = cp[(k << 5) + lane];
            sum0 = fmaf(v.x, h_sm[cc & 0xFFFFu], sum0);
            sum1 = fmaf(v.y, h_sm[cc >> 16],     sum1);
        }

        // butterfly warp reduce
        float sum = sum0 + sum1;
        #pragma unroll
        for (int o = 16; o > 0; o >>= 1)
            sum += __shfl_xor_sync(0xffffffffu, sum, o);

        if (lane == 0) {
            float hn = ia * h_sm[row] + a * tanhf(sum);
            __stcg(out + (size_t)t * N_RES + row, hn);
        }

        if (t < T_STEPS - 1) {
            __syncthreads();                 // all 32 rows published (st.cg in L2)
            if (tid == 0) red_release_gpu_add(&g_barrier, 1u);
        }
    }
}

extern "C" void kernel_launch(void* const* d_in, const int* in_sizes, int n_in,
                              void* d_out, int out_size)
{
    const float* x    = (const float*)d_in[0];   // [2048, 128]
    const float* W_in = (const float*)d_in[1];   // [4096, 128]
    const float* W    = (const float*)d_in[2];   // [4096, 4096]
    float* out        = (float*)d_out;           // [2048, 4096]

    esn_reset_kernel<<<1, 1>>>();
    esn_kernel<<<BLOCKS, THREADS>>>(x, W_in, W, out);
}